// round 1
// baseline (speedup 1.0000x reference)
#include <cuda_runtime.h>
#include <cstdint>
#include <cstddef>

// ----------------------------------------------------------------------------
// Problem constants: B=32, S=512, E=512, U=1024, G=4*U=4096
// out = (h, h, c)  -> 3 * 32 * 1024 floats
// ----------------------------------------------------------------------------

#define NCTA     128     // persistent CTAs (<=148 SMs -> all co-resident)
#define KSPLIT   8       // k-splits of 128
#define JBLK     16      // j-blocks of 256

// ---- device scratch (static allocation; no cudaMalloc allowed) --------------
__device__ float g_xw[(size_t)16384 * 4096];     // xW, layout [t*32+b][4096] (268MB)
__device__ float g_part[KSPLIT][32][4096];       // split-K partials (4MB)
__device__ float g_hT[2][32768];                 // h double buffer, layout [k*32+b]
__device__ int   g_tokens[16384];                // normalized int32 tokens [b*512+t]
__device__ unsigned g_cnt;                       // grid barrier counter
__device__ volatile unsigned g_gen;              // grid barrier generation

// ----------------------------------------------------------------------------
// Token normalization: the reference asks for int64 tokens, but jax without
// x64 silently produces int32. Detect on-device (int64 little-endian high
// words of first 256 entries all zero) and convert to int32.
// ----------------------------------------------------------------------------
__global__ void token_convert_kernel(const int* __restrict__ raw)
{
    __shared__ int s_is64;
    if (threadIdx.x == 0) s_is64 = 1;
    __syncthreads();
    if (threadIdx.x < 256) {
        if (raw[2 * threadIdx.x + 1] != 0) s_is64 = 0;  // benign race: all write 0
    }
    __syncthreads();
    const int is64 = s_is64;
    for (int i = threadIdx.x; i < 16384; i += blockDim.x)
        g_tokens[i] = is64 ? raw[2 * i] : raw[i];
}

// ----------------------------------------------------------------------------
// Kernel 1: fused embedding gather + GEMM:  g_xw[r][n] = emb[tok(r)] @ W + b
// r = t*32 + b (time-major rows so the scan reads contiguous 32x4096 slabs).
// Tiles: BM=64, BN=128, BK=16, 256 threads, 4m x 8n register tile.
// ----------------------------------------------------------------------------
__global__ void __launch_bounds__(256) embed_gemm_kernel(
    const float* __restrict__ emb,
    const float* __restrict__ W,
    const float* __restrict__ bias)
{
    __shared__ float as[16][65];    // [kk][m], pitch 65 -> conflict-free stores
    __shared__ float bs[16][128];   // [kk][n]

    const int thr = threadIdx.x;
    const int n0  = blockIdx.x * 128;
    const int m0  = blockIdx.y * 64;
    const int my  = thr >> 4;   // 0..15  (m group of 4)
    const int nx  = thr & 15;   // 0..15  (n group of 4+4)

    // A-tile loader mapping: lkk = k within chunk, lm(+p*16) = row
    const int lkk = thr & 15;
    const int lm  = thr >> 4;

    const float* arow[4];
#pragma unroll
    for (int p = 0; p < 4; ++p) {
        int r   = m0 + lm + p * 16;
        int b   = r & 31;
        int t   = r >> 5;
        int tok = g_tokens[b * 512 + t];
        arow[p] = emb + (size_t)tok * 512;
    }

    float acc[4][8];
#pragma unroll
    for (int i = 0; i < 4; ++i)
#pragma unroll
        for (int j = 0; j < 8; ++j) acc[i][j] = 0.f;

    for (int k0 = 0; k0 < 512; k0 += 16) {
#pragma unroll
        for (int p = 0; p < 4; ++p)
            as[lkk][lm + p * 16] = arow[p][k0 + lkk];
#pragma unroll
        for (int p = 0; p < 2; ++p) {
            int i  = p * 256 + thr;
            int kk = i >> 5;
            int c4 = i & 31;
            ((float4*)&bs[kk][0])[c4] =
                ((const float4*)(W + (size_t)(k0 + kk) * 4096 + n0))[c4];
        }
        __syncthreads();
#pragma unroll
        for (int kk = 0; kk < 16; ++kk) {
            float av[4];
#pragma unroll
            for (int q = 0; q < 4; ++q) av[q] = as[kk][my * 4 + q];
            float4 b0 = *(const float4*)&bs[kk][nx * 4];
            float4 b1 = *(const float4*)&bs[kk][64 + nx * 4];
            float bv[8] = {b0.x, b0.y, b0.z, b0.w, b1.x, b1.y, b1.z, b1.w};
#pragma unroll
            for (int i = 0; i < 4; ++i)
#pragma unroll
                for (int j = 0; j < 8; ++j)
                    acc[i][j] = fmaf(av[i], bv[j], acc[i][j]);
        }
        __syncthreads();
    }

    float4 bb0 = *(const float4*)&bias[n0 + nx * 4];
    float4 bb1 = *(const float4*)&bias[n0 + 64 + nx * 4];
#pragma unroll
    for (int q = 0; q < 4; ++q) {
        size_t r = (size_t)(m0 + my * 4 + q);
        float* o = g_xw + r * 4096 + n0;
        float4 v0 = make_float4(acc[q][0] + bb0.x, acc[q][1] + bb0.y,
                                acc[q][2] + bb0.z, acc[q][3] + bb0.w);
        float4 v1 = make_float4(acc[q][4] + bb1.x, acc[q][5] + bb1.y,
                                acc[q][6] + bb1.z, acc[q][7] + bb1.w);
        *(float4*)(o + nx * 4)      = v0;
        *(float4*)(o + 64 + nx * 4) = v1;
    }
}

// ----------------------------------------------------------------------------
// Software grid barrier for the persistent LSTM kernel (all NCTA resident).
// Every thread fences its own writes; thread 0 arrives; classic gen/count.
// ----------------------------------------------------------------------------
__device__ __forceinline__ void grid_barrier()
{
    __threadfence();
    __syncthreads();
    if (threadIdx.x == 0) {
        unsigned g = g_gen;
        if (atomicAdd(&g_cnt, 1u) == (NCTA - 1u)) {
            g_cnt = 0;
            __threadfence();
            g_gen = g + 1;
        } else {
            while (g_gen == g) { __nanosleep(64); }
        }
    }
    __syncthreads();
}

// ----------------------------------------------------------------------------
// Kernel 2: persistent LSTM scan.
// Phase 1 (per step): split-K GEMM  part[ks][b][j] = sum_{k in ks} h[b,k]*U[k,j]
//   CTA (ks, jb): k-range 128, j-range 256. 256 thr, each 4b x 8j registers.
// Phase 2: each of the 32768 threads owns one (b,u); reduces 8 partials x 4
//   gates + xW, applies tanh gates + mask, keeps h,c in registers, publishes
//   h to the transposed double buffer g_hT[(t+1)&1][u*32+b].
// Cross-step global data uses __ldcg (L1 is not coherent inside one launch).
// ----------------------------------------------------------------------------
__global__ void __launch_bounds__(256, 1) lstm_kernel(
    const float* __restrict__ U,
    float* __restrict__ out)
{
    __shared__ float hs[16][32];    // h chunk [kk][b]
    __shared__ float us[16][256];   // U chunk [kk][j]

    const int thr   = threadIdx.x;
    const int cta   = blockIdx.x;
    const int tx    = thr & 31;     // j group (4 + 4 cols, offset 128)
    const int ty    = thr >> 5;     // b group of 4
    const int jb    = cta & (JBLK - 1);
    const int ks    = cta >> 4;
    const int jbase = jb << 8;      // *256
    const int kbase = ks << 7;      // *128

    // phase-2 ownership: one (b,u) per thread across the whole grid
    const int tid   = cta * 256 + thr;
    const int u_idx = tid & 1023;
    const int b_idx = tid >> 10;
    const int* tokrow = g_tokens + b_idx * 512;

    float hreg = 0.f, creg = 0.f;

    g_hT[0][tid] = 0.f;              // zero initial h (exactly one elem each)
    grid_barrier();

    for (int t = 0; t < 512; ++t) {
        const float* hcur = g_hT[t & 1];

        // ---------------- phase 1: partial GEMM ----------------
        float acc[4][8];
#pragma unroll
        for (int i = 0; i < 4; ++i)
#pragma unroll
            for (int j = 0; j < 8; ++j) acc[i][j] = 0.f;

        for (int kc = 0; kc < 128; kc += 16) {
            const int k0 = kbase + kc;
            if (thr < 128) {
                float4 hv = __ldcg(((const float4*)(hcur + (size_t)k0 * 32)) + thr);
                ((float4*)hs)[thr] = hv;
            }
#pragma unroll
            for (int p = 0; p < 2; ++p) {
                int i  = p * 256 + thr;
                int kk = i >> 6;
                int c4 = i & 63;
                ((float4*)us)[kk * 64 + c4] =
                    *(((const float4*)(U + (size_t)(k0 + kk) * 4096 + jbase)) + c4);
            }
            __syncthreads();
#pragma unroll
            for (int kk = 0; kk < 16; ++kk) {
                float4 hv = *(const float4*)&hs[kk][ty * 4];
                float4 u0 = *(const float4*)&us[kk][tx * 4];
                float4 u1 = *(const float4*)&us[kk][128 + tx * 4];
                float av[4] = {hv.x, hv.y, hv.z, hv.w};
                float bv[8] = {u0.x, u0.y, u0.z, u0.w, u1.x, u1.y, u1.z, u1.w};
#pragma unroll
                for (int i = 0; i < 4; ++i)
#pragma unroll
                    for (int j = 0; j < 8; ++j)
                        acc[i][j] = fmaf(av[i], bv[j], acc[i][j]);
            }
            __syncthreads();
        }

#pragma unroll
        for (int bb = 0; bb < 4; ++bb) {
            int bRow = ty * 4 + bb;
            float* prow = &g_part[ks][bRow][jbase];
            *(float4*)(prow + tx * 4) =
                make_float4(acc[bb][0], acc[bb][1], acc[bb][2], acc[bb][3]);
            *(float4*)(prow + 128 + tx * 4) =
                make_float4(acc[bb][4], acc[bb][5], acc[bb][6], acc[bb][7]);
        }
        grid_barrier();

        // ---------------- phase 2: reduce + gates ----------------
        {
            const float* xwrow = g_xw + ((size_t)t * 32 + b_idx) * 4096;
            float z[4];
#pragma unroll
            for (int g = 0; g < 4; ++g) {
                int col = u_idx + g * 1024;
                float s = __ldcs(xwrow + col);
#pragma unroll
                for (int kr = 0; kr < KSPLIT; ++kr)
                    s += __ldcg(&g_part[kr][b_idx][col]);
                z[g] = s;
            }
            float gi = tanhf(z[0]);
            float gf = tanhf(z[1]);
            float gg = tanhf(z[2]);
            float go = tanhf(z[3]);
            float cn = fmaf(gf, creg, gi * gg);
            float hn = go * tanhf(cn);
            if (tokrow[t] != 0) { creg = cn; hreg = hn; }
            g_hT[(t + 1) & 1][u_idx * 32 + b_idx] = hreg;
        }
        grid_barrier();
    }

    // output: (h, h, c), each [b][u]
    out[b_idx * 1024 + u_idx]         = hreg;
    out[32768 + b_idx * 1024 + u_idx] = hreg;
    out[65536 + b_idx * 1024 + u_idx] = creg;
}

// ----------------------------------------------------------------------------
// launch: tokens, emb, W, U, b  ->  out (3*32*1024 f32)
// ----------------------------------------------------------------------------
extern "C" void kernel_launch(void* const* d_in, const int* in_sizes, int n_in,
                              void* d_out, int out_size)
{
    const int*   tokens_raw = (const int*)  d_in[0];   // int64 or int32, detected
    const float* emb        = (const float*)d_in[1];
    const float* W          = (const float*)d_in[2];
    const float* U          = (const float*)d_in[3];
    const float* bias       = (const float*)d_in[4];
    float*       out        = (float*)d_out;
    (void)in_sizes; (void)n_in; (void)out_size;

    token_convert_kernel<<<1, 256>>>(tokens_raw);
    embed_gemm_kernel<<<dim3(32, 256), 256>>>(emb, W, bias);
    lstm_kernel<<<NCTA, 256>>>(U, out);
}

// round 2
// speedup vs baseline: 1.0500x; 1.0500x over previous
#include <cuda_runtime.h>
#include <cstdint>
#include <cstddef>

// ----------------------------------------------------------------------------
// B=32, S=512, E=512, U=1024, G=4096.  out = (h, h, c) : 3*32*1024 f32
// ----------------------------------------------------------------------------
#define NCTA    128
#define KSPLIT  16      // k-splits of 64
#define JBLK    8       // j-blocks of 512

__device__ float g_xw[(size_t)16384 * 4096];   // xW rows [t*32+b][4096]
__device__ float g_part[KSPLIT][32][4096];     // split-K partials
__device__ float g_hT[2][32768];               // h double buffer [k*32+b]
__device__ int   g_tokens[16384];              // int32 tokens [b*512+t]
__device__ unsigned g_cnt;
__device__ volatile unsigned g_gen;

// int64-vs-int32 token detection: int64 tokens have zero high words; int32
// data would need 128 specific tokens to all be 0 (prob ~ (1/32000)^128).
__device__ __forceinline__ int detect_is64(const int* raw, int thr, int* s_flag)
{
    if (thr == 0) *s_flag = 1;
    __syncthreads();
    if (thr < 128 && raw[2 * thr + 1] != 0) *s_flag = 0;
    __syncthreads();
    return *s_flag;
}

// ----------------------------------------------------------------------------
// Kernel 1: fused embedding gather + GEMM  g_xw[r][n] = emb[tok(r)] @ W + b
// r = t*32 + b.  BM=128, BN=128, BK=16, 256 thr, 8x8 micro, double-buffered.
// ----------------------------------------------------------------------------
__global__ void __launch_bounds__(256) embed_gemm_kernel(
    const int*   __restrict__ raw,
    const float* __restrict__ emb,
    const float* __restrict__ W,
    const float* __restrict__ bias)
{
    __shared__ float As[2][16][132];   // [k][m], pitch 132 (16B aligned, low conflict)
    __shared__ float Bs[2][16][128];   // [k][n]
    __shared__ int s_is64;

    const int thr = threadIdx.x;
    const int is64 = detect_is64(raw, thr, &s_is64);

    const int n0 = blockIdx.x * 128;
    const int m0 = blockIdx.y * 128;
    const int tx = thr & 15;
    const int ty = thr >> 4;

    // A loader: 2 float4 (along k) per stage per thread
    const float* aptr[2];
    int akq[2], am[2];
#pragma unroll
    for (int p = 0; p < 2; ++p) {
        int idx = p * 256 + thr;
        am[p]  = idx >> 2;
        akq[p] = idx & 3;
        int r  = m0 + am[p];
        int ti = (r & 31) * 512 + (r >> 5);
        int tok = is64 ? raw[2 * ti] : raw[ti];
        aptr[p] = emb + (size_t)tok * 512;
    }
    // B loader: 2 float4 per stage per thread
    int bkk[2], bc4[2];
#pragma unroll
    for (int p = 0; p < 2; ++p) {
        int idx = p * 256 + thr;
        bkk[p] = idx >> 5;
        bc4[p] = idx & 31;
    }

    // stage 0 -> buffer 0
#pragma unroll
    for (int p = 0; p < 2; ++p) {
        float4 v = *(const float4*)(aptr[p] + akq[p] * 4);
        As[0][akq[p] * 4 + 0][am[p]] = v.x;
        As[0][akq[p] * 4 + 1][am[p]] = v.y;
        As[0][akq[p] * 4 + 2][am[p]] = v.z;
        As[0][akq[p] * 4 + 3][am[p]] = v.w;
        float4 w4 = *(const float4*)(W + (size_t)bkk[p] * 4096 + n0 + bc4[p] * 4);
        *(float4*)&Bs[0][bkk[p]][bc4[p] * 4] = w4;
    }
    __syncthreads();

    float acc[8][8];
#pragma unroll
    for (int i = 0; i < 8; ++i)
#pragma unroll
        for (int j = 0; j < 8; ++j) acc[i][j] = 0.f;

    int buf = 0;
    for (int k0 = 0; k0 < 512; k0 += 16) {
        float4 an[2], bn[2];
        const bool more = (k0 + 16) < 512;
        if (more) {
#pragma unroll
            for (int p = 0; p < 2; ++p) {
                an[p] = *(const float4*)(aptr[p] + k0 + 16 + akq[p] * 4);
                bn[p] = *(const float4*)(W + (size_t)(k0 + 16 + bkk[p]) * 4096 + n0 + bc4[p] * 4);
            }
        }
#pragma unroll
        for (int kk = 0; kk < 16; ++kk) {
            float4 a0 = *(const float4*)&As[buf][kk][ty * 4];
            float4 a1 = *(const float4*)&As[buf][kk][64 + ty * 4];
            float4 b0 = *(const float4*)&Bs[buf][kk][tx * 4];
            float4 b1 = *(const float4*)&Bs[buf][kk][64 + tx * 4];
            float av[8] = {a0.x, a0.y, a0.z, a0.w, a1.x, a1.y, a1.z, a1.w};
            float bv[8] = {b0.x, b0.y, b0.z, b0.w, b1.x, b1.y, b1.z, b1.w};
#pragma unroll
            for (int i = 0; i < 8; ++i)
#pragma unroll
                for (int j = 0; j < 8; ++j)
                    acc[i][j] = fmaf(av[i], bv[j], acc[i][j]);
        }
        if (more) {
            int nb = buf ^ 1;
#pragma unroll
            for (int p = 0; p < 2; ++p) {
                As[nb][akq[p] * 4 + 0][am[p]] = an[p].x;
                As[nb][akq[p] * 4 + 1][am[p]] = an[p].y;
                As[nb][akq[p] * 4 + 2][am[p]] = an[p].z;
                As[nb][akq[p] * 4 + 3][am[p]] = an[p].w;
                *(float4*)&Bs[nb][bkk[p]][bc4[p] * 4] = bn[p];
            }
        }
        __syncthreads();
        buf ^= 1;
    }

    float4 bb0 = *(const float4*)(bias + n0 + tx * 4);
    float4 bb1 = *(const float4*)(bias + n0 + 64 + tx * 4);
#pragma unroll
    for (int i = 0; i < 8; ++i) {
        int m = (i < 4) ? (ty * 4 + i) : (64 + ty * 4 + i - 4);
        float* o = g_xw + (size_t)(m0 + m) * 4096 + n0;
        *(float4*)(o + tx * 4) = make_float4(acc[i][0] + bb0.x, acc[i][1] + bb0.y,
                                             acc[i][2] + bb0.z, acc[i][3] + bb0.w);
        *(float4*)(o + 64 + tx * 4) = make_float4(acc[i][4] + bb1.x, acc[i][5] + bb1.y,
                                                  acc[i][6] + bb1.z, acc[i][7] + bb1.w);
    }
}

// ----------------------------------------------------------------------------
// Grid barrier (replay-safe: counter returns to 0, gen monotonic)
// ----------------------------------------------------------------------------
__device__ __forceinline__ void grid_barrier()
{
    __threadfence();
    __syncthreads();
    if (threadIdx.x == 0) {
        unsigned g = g_gen;
        if (atomicAdd(&g_cnt, 1u) == (NCTA - 1u)) {
            g_cnt = 0;
            __threadfence();
            g_gen = g + 1;
        } else {
            while (g_gen == g) { __nanosleep(32); }
        }
    }
    __syncthreads();
}

// ----------------------------------------------------------------------------
// Kernel 2: persistent LSTM scan.
// Phase 1: CTA (ks,jb) computes part[ks][b][j] over k in [ks*64, ks*64+64),
//          j in [jb*512, jb*512+512).  8b x 8j register tile (FMA-bound).
// Phase 2: thread (b,u) reduces 16 partials x 4 gates + prefetched xW,
//          applies tanh gates + mask, publishes h to transposed buffer.
// ----------------------------------------------------------------------------
__global__ void __launch_bounds__(256, 1) lstm_kernel(
    const int*   __restrict__ raw,
    const float* __restrict__ U,
    float*       __restrict__ out)
{
    __shared__ float us[16][512];   // U chunk [kk][j] (32KB)
    __shared__ float hs[16][32];    // h chunk [kk][b]
    __shared__ int s_is64;

    const int thr = threadIdx.x;
    const int cta = blockIdx.x;
    const int is64 = detect_is64(raw, thr, &s_is64);

    const int tx    = thr & 63;     // j group
    const int ty    = thr >> 6;     // b group
    const int ks    = cta >> 3;
    const int jb    = cta & 7;
    const int kbase = ks << 6;      // *64
    const int jbase = jb << 9;      // *512

    const int tid   = cta * 256 + thr;
    const int u_idx = tid & 1023;
    const int b_idx = tid >> 10;

    // prologue: convert this CTA's token slice, zero h buffer 0
    if (thr < 128) {
        int i = cta * 128 + thr;
        g_tokens[i] = is64 ? raw[2 * i] : raw[i];
    }
    g_hT[0][tid] = 0.f;
    grid_barrier();

    float hreg = 0.f, creg = 0.f;

    // prefetch t=0 gate inputs
    float xwp[4];
    int tokv;
    {
        const float* xr = g_xw + (size_t)b_idx * 4096;
#pragma unroll
        for (int g = 0; g < 4; ++g) xwp[g] = __ldcs(xr + u_idx + g * 1024);
        tokv = g_tokens[b_idx * 512];
    }

    for (int t = 0; t < 512; ++t) {
        const float* hcur = g_hT[t & 1];

        // ------------- phase 1: split-K GEMM -------------
        float acc[8][8];
#pragma unroll
        for (int i = 0; i < 8; ++i)
#pragma unroll
            for (int j = 0; j < 8; ++j) acc[i][j] = 0.f;

        for (int kc = 0; kc < 64; kc += 16) {
            const int k0 = kbase + kc;
            if (thr < 128) {
                int kk = thr >> 3, b4 = thr & 7;
                float4 hv = __ldcg((const float4*)(hcur + (size_t)(k0 + kk) * 32) + b4);
                *(float4*)&hs[kk][b4 * 4] = hv;
            }
#pragma unroll
            for (int it = 0; it < 8; ++it) {
                int i  = it * 256 + thr;
                int kk = i >> 7;
                int c4 = i & 127;
                float4 uv = *(const float4*)(U + (size_t)(k0 + kk) * 4096 + jbase + c4 * 4);
                *(float4*)&us[kk][c4 * 4] = uv;
            }
            __syncthreads();
#pragma unroll
            for (int kk = 0; kk < 16; ++kk) {
                float4 a0 = *(const float4*)&hs[kk][ty * 4];
                float4 a1 = *(const float4*)&hs[kk][16 + ty * 4];
                float4 b0 = *(const float4*)&us[kk][tx * 4];
                float4 b1 = *(const float4*)&us[kk][256 + tx * 4];
                float av[8] = {a0.x, a0.y, a0.z, a0.w, a1.x, a1.y, a1.z, a1.w};
                float bv[8] = {b0.x, b0.y, b0.z, b0.w, b1.x, b1.y, b1.z, b1.w};
#pragma unroll
                for (int i = 0; i < 8; ++i)
#pragma unroll
                    for (int j = 0; j < 8; ++j)
                        acc[i][j] = fmaf(av[i], bv[j], acc[i][j]);
            }
            __syncthreads();
        }

        // store partials (coalesced: lanes tx*4 contiguous)
#pragma unroll
        for (int i = 0; i < 8; ++i) {
            int brow = (i < 4) ? (ty * 4 + i) : (16 + ty * 4 + i - 4);
            float* p = &g_part[ks][brow][jbase];
            *(float4*)(p + tx * 4)       = make_float4(acc[i][0], acc[i][1], acc[i][2], acc[i][3]);
            *(float4*)(p + 256 + tx * 4) = make_float4(acc[i][4], acc[i][5], acc[i][6], acc[i][7]);
        }
        grid_barrier();

        // ------------- phase 2: reduce + gates -------------
        {
            float z0 = xwp[0], z1 = xwp[1], z2 = xwp[2], z3 = xwp[3];
#pragma unroll
            for (int kr = 0; kr < KSPLIT; ++kr) {
                z0 += __ldcg(&g_part[kr][b_idx][u_idx]);
                z1 += __ldcg(&g_part[kr][b_idx][u_idx + 1024]);
                z2 += __ldcg(&g_part[kr][b_idx][u_idx + 2048]);
                z3 += __ldcg(&g_part[kr][b_idx][u_idx + 3072]);
            }
            float gi = tanhf(z0);
            float gf = tanhf(z1);
            float gg = tanhf(z2);
            float go = tanhf(z3);
            float cn = fmaf(gf, creg, gi * gg);
            float hn = go * tanhf(cn);
            if (tokv != 0) { creg = cn; hreg = hn; }
            g_hT[(t + 1) & 1][u_idx * 32 + b_idx] = hreg;

            // prefetch next step's gate inputs (off the critical path)
            if (t + 1 < 512) {
                const float* xr = g_xw + ((size_t)(t + 1) * 32 + b_idx) * 4096;
#pragma unroll
                for (int g = 0; g < 4; ++g) xwp[g] = __ldcs(xr + u_idx + g * 1024);
                tokv = g_tokens[b_idx * 512 + t + 1];
            }
        }
        grid_barrier();
    }

    out[b_idx * 1024 + u_idx]         = hreg;
    out[32768 + b_idx * 1024 + u_idx] = hreg;
    out[65536 + b_idx * 1024 + u_idx] = creg;
}

// ----------------------------------------------------------------------------
extern "C" void kernel_launch(void* const* d_in, const int* in_sizes, int n_in,
                              void* d_out, int out_size)
{
    const int*   tokens_raw = (const int*)  d_in[0];
    const float* emb        = (const float*)d_in[1];
    const float* W          = (const float*)d_in[2];
    const float* U          = (const float*)d_in[3];
    const float* bias       = (const float*)d_in[4];
    float*       out        = (float*)d_out;
    (void)in_sizes; (void)n_in; (void)out_size;

    embed_gemm_kernel<<<dim3(32, 128), 256>>>(tokens_raw, emb, W, bias);
    lstm_kernel<<<NCTA, 256>>>(tokens_raw, U, out);
}

// round 3
// speedup vs baseline: 1.0533x; 1.0031x over previous
#include <cuda_runtime.h>
#include <cstdint>
#include <cstddef>

// ----------------------------------------------------------------------------
// B=32, S=512, E=512, U=1024, G=4096.  out = (h, h, c) : 3*32*1024 f32
// ----------------------------------------------------------------------------
#define NCTA    128
#define KSPLIT  16      // k-splits of 64
#define JBLK    8       // j-blocks of 512

__device__ float g_xw[(size_t)16384 * 4096];   // xW rows [t*32+b][4096]
__device__ float g_part[KSPLIT][32][4096];     // split-K partials
__device__ float g_hT[2][32768];               // h double buffer [k*32+b]
__device__ int   g_tokens[16384];              // int32 tokens [b*512+t]
__device__ unsigned g_cnt;
__device__ volatile unsigned g_gen;

// int64-vs-int32 token detection: int64 tokens have zero high words; int32
// data would need 128 specific tokens to all be 0 (prob ~ (1/32000)^128).
__device__ __forceinline__ int detect_is64(const int* raw, int thr, int* s_flag)
{
    if (thr == 0) *s_flag = 1;
    __syncthreads();
    if (thr < 128 && raw[2 * thr + 1] != 0) *s_flag = 0;
    __syncthreads();
    return *s_flag;
}

// ----------------------------------------------------------------------------
// Kernel 1: fused embedding gather + GEMM  g_xw[r][n] = emb[tok(r)] @ W + b
// r = t*32 + b.  BM=128, BN=128, BK=16, 256 thr, 8x8 micro, double-buffered.
// ----------------------------------------------------------------------------
__global__ void __launch_bounds__(256) embed_gemm_kernel(
    const int*   __restrict__ raw,
    const float* __restrict__ emb,
    const float* __restrict__ W,
    const float* __restrict__ bias)
{
    __shared__ float As[2][16][132];   // [k][m], pitch 132 (16B aligned, low conflict)
    __shared__ float Bs[2][16][128];   // [k][n]
    __shared__ int s_is64;

    const int thr = threadIdx.x;
    const int is64 = detect_is64(raw, thr, &s_is64);

    const int n0 = blockIdx.x * 128;
    const int m0 = blockIdx.y * 128;
    const int tx = thr & 15;
    const int ty = thr >> 4;

    // A loader: 2 float4 (along k) per stage per thread
    const float* aptr[2];
    int akq[2], am[2];
#pragma unroll
    for (int p = 0; p < 2; ++p) {
        int idx = p * 256 + thr;
        am[p]  = idx >> 2;
        akq[p] = idx & 3;
        int r  = m0 + am[p];
        int ti = (r & 31) * 512 + (r >> 5);
        int tok = is64 ? raw[2 * ti] : raw[ti];
        aptr[p] = emb + (size_t)tok * 512;
    }
    // B loader: 2 float4 per stage per thread
    int bkk[2], bc4[2];
#pragma unroll
    for (int p = 0; p < 2; ++p) {
        int idx = p * 256 + thr;
        bkk[p] = idx >> 5;
        bc4[p] = idx & 31;
    }

    // stage 0 -> buffer 0
#pragma unroll
    for (int p = 0; p < 2; ++p) {
        float4 v = *(const float4*)(aptr[p] + akq[p] * 4);
        As[0][akq[p] * 4 + 0][am[p]] = v.x;
        As[0][akq[p] * 4 + 1][am[p]] = v.y;
        As[0][akq[p] * 4 + 2][am[p]] = v.z;
        As[0][akq[p] * 4 + 3][am[p]] = v.w;
        float4 w4 = *(const float4*)(W + (size_t)bkk[p] * 4096 + n0 + bc4[p] * 4);
        *(float4*)&Bs[0][bkk[p]][bc4[p] * 4] = w4;
    }
    __syncthreads();

    float acc[8][8];
#pragma unroll
    for (int i = 0; i < 8; ++i)
#pragma unroll
        for (int j = 0; j < 8; ++j) acc[i][j] = 0.f;

    int buf = 0;
    for (int k0 = 0; k0 < 512; k0 += 16) {
        float4 an[2], bn[2];
        const bool more = (k0 + 16) < 512;
        if (more) {
#pragma unroll
            for (int p = 0; p < 2; ++p) {
                an[p] = *(const float4*)(aptr[p] + k0 + 16 + akq[p] * 4);
                bn[p] = *(const float4*)(W + (size_t)(k0 + 16 + bkk[p]) * 4096 + n0 + bc4[p] * 4);
            }
        }
#pragma unroll
        for (int kk = 0; kk < 16; ++kk) {
            float4 a0 = *(const float4*)&As[buf][kk][ty * 4];
            float4 a1 = *(const float4*)&As[buf][kk][64 + ty * 4];
            float4 b0 = *(const float4*)&Bs[buf][kk][tx * 4];
            float4 b1 = *(const float4*)&Bs[buf][kk][64 + tx * 4];
            float av[8] = {a0.x, a0.y, a0.z, a0.w, a1.x, a1.y, a1.z, a1.w};
            float bv[8] = {b0.x, b0.y, b0.z, b0.w, b1.x, b1.y, b1.z, b1.w};
#pragma unroll
            for (int i = 0; i < 8; ++i)
#pragma unroll
                for (int j = 0; j < 8; ++j)
                    acc[i][j] = fmaf(av[i], bv[j], acc[i][j]);
        }
        if (more) {
            int nb = buf ^ 1;
#pragma unroll
            for (int p = 0; p < 2; ++p) {
                As[nb][akq[p] * 4 + 0][am[p]] = an[p].x;
                As[nb][akq[p] * 4 + 1][am[p]] = an[p].y;
                As[nb][akq[p] * 4 + 2][am[p]] = an[p].z;
                As[nb][akq[p] * 4 + 3][am[p]] = an[p].w;
                *(float4*)&Bs[nb][bkk[p]][bc4[p] * 4] = bn[p];
            }
        }
        __syncthreads();
        buf ^= 1;
    }

    float4 bb0 = *(const float4*)(bias + n0 + tx * 4);
    float4 bb1 = *(const float4*)(bias + n0 + 64 + tx * 4);
#pragma unroll
    for (int i = 0; i < 8; ++i) {
        int m = (i < 4) ? (ty * 4 + i) : (64 + ty * 4 + i - 4);
        float* o = g_xw + (size_t)(m0 + m) * 4096 + n0;
        *(float4*)(o + tx * 4) = make_float4(acc[i][0] + bb0.x, acc[i][1] + bb0.y,
                                             acc[i][2] + bb0.z, acc[i][3] + bb0.w);
        *(float4*)(o + 64 + tx * 4) = make_float4(acc[i][4] + bb1.x, acc[i][5] + bb1.y,
                                                  acc[i][6] + bb1.z, acc[i][7] + bb1.w);
    }
}

// ----------------------------------------------------------------------------
// Grid barrier (replay-safe: counter returns to 0, gen monotonic)
// ----------------------------------------------------------------------------
__device__ __forceinline__ void grid_barrier()
{
    __threadfence();
    __syncthreads();
    if (threadIdx.x == 0) {
        unsigned g = g_gen;
        if (atomicAdd(&g_cnt, 1u) == (NCTA - 1u)) {
            g_cnt = 0;
            __threadfence();
            g_gen = g + 1;
        } else {
            while (g_gen == g) { __nanosleep(32); }
        }
    }
    __syncthreads();
}

// ----------------------------------------------------------------------------
// Kernel 2: persistent LSTM scan.
// Phase 1: CTA (ks,jb) computes part[ks][b][j] over k in [ks*64, ks*64+64),
//          j in [jb*512, jb*512+512).  8b x 8j register tile (FMA-bound).
// Phase 2: thread (b,u) reduces 16 partials x 4 gates + prefetched xW,
//          applies tanh gates + mask, publishes h to transposed buffer.
// ----------------------------------------------------------------------------
__global__ void __launch_bounds__(256, 1) lstm_kernel(
    const int*   __restrict__ raw,
    const float* __restrict__ U,
    float*       __restrict__ out)
{
    __shared__ float us[16][512];   // U chunk [kk][j] (32KB)
    __shared__ float hs[16][32];    // h chunk [kk][b]
    __shared__ int s_is64;

    const int thr = threadIdx.x;
    const int cta = blockIdx.x;
    const int is64 = detect_is64(raw, thr, &s_is64);

    const int tx    = thr & 63;     // j group
    const int ty    = thr >> 6;     // b group
    const int ks    = cta >> 3;
    const int jb    = cta & 7;
    const int kbase = ks << 6;      // *64
    const int jbase = jb << 9;      // *512

    const int tid   = cta * 256 + thr;
    const int u_idx = tid & 1023;
    const int b_idx = tid >> 10;

    // prologue: convert this CTA's token slice, zero h buffer 0
    if (thr < 128) {
        int i = cta * 128 + thr;
        g_tokens[i] = is64 ? raw[2 * i] : raw[i];
    }
    g_hT[0][tid] = 0.f;
    grid_barrier();

    float hreg = 0.f, creg = 0.f;

    // prefetch t=0 gate inputs
    float xwp[4];
    int tokv;
    {
        const float* xr = g_xw + (size_t)b_idx * 4096;
#pragma unroll
        for (int g = 0; g < 4; ++g) xwp[g] = __ldcs(xr + u_idx + g * 1024);
        tokv = g_tokens[b_idx * 512];
    }

    for (int t = 0; t < 512; ++t) {
        const float* hcur = g_hT[t & 1];

        // ------------- phase 1: split-K GEMM -------------
        float acc[8][8];
#pragma unroll
        for (int i = 0; i < 8; ++i)
#pragma unroll
            for (int j = 0; j < 8; ++j) acc[i][j] = 0.f;

        for (int kc = 0; kc < 64; kc += 16) {
            const int k0 = kbase + kc;
            if (thr < 128) {
                int kk = thr >> 3, b4 = thr & 7;
                float4 hv = __ldcg((const float4*)(hcur + (size_t)(k0 + kk) * 32) + b4);
                *(float4*)&hs[kk][b4 * 4] = hv;
            }
#pragma unroll
            for (int it = 0; it < 8; ++it) {
                int i  = it * 256 + thr;
                int kk = i >> 7;
                int c4 = i & 127;
                float4 uv = *(const float4*)(U + (size_t)(k0 + kk) * 4096 + jbase + c4 * 4);
                *(float4*)&us[kk][c4 * 4] = uv;
            }
            __syncthreads();
#pragma unroll
            for (int kk = 0; kk < 16; ++kk) {
                float4 a0 = *(const float4*)&hs[kk][ty * 4];
                float4 a1 = *(const float4*)&hs[kk][16 + ty * 4];
                float4 b0 = *(const float4*)&us[kk][tx * 4];
                float4 b1 = *(const float4*)&us[kk][256 + tx * 4];
                float av[8] = {a0.x, a0.y, a0.z, a0.w, a1.x, a1.y, a1.z, a1.w};
                float bv[8] = {b0.x, b0.y, b0.z, b0.w, b1.x, b1.y, b1.z, b1.w};
#pragma unroll
                for (int i = 0; i < 8; ++i)
#pragma unroll
                    for (int j = 0; j < 8; ++j)
                        acc[i][j] = fmaf(av[i], bv[j], acc[i][j]);
            }
            __syncthreads();
        }

        // store partials (coalesced: lanes tx*4 contiguous)
#pragma unroll
        for (int i = 0; i < 8; ++i) {
            int brow = (i < 4) ? (ty * 4 + i) : (16 + ty * 4 + i - 4);
            float* p = &g_part[ks][brow][jbase];
            *(float4*)(p + tx * 4)       = make_float4(acc[i][0], acc[i][1], acc[i][2], acc[i][3]);
            *(float4*)(p + 256 + tx * 4) = make_float4(acc[i][4], acc[i][5], acc[i][6], acc[i][7]);
        }
        grid_barrier();

        // ------------- phase 2: reduce + gates -------------
        {
            float z0 = xwp[0], z1 = xwp[1], z2 = xwp[2], z3 = xwp[3];
#pragma unroll
            for (int kr = 0; kr < KSPLIT; ++kr) {
                z0 += __ldcg(&g_part[kr][b_idx][u_idx]);
                z1 += __ldcg(&g_part[kr][b_idx][u_idx + 1024]);
                z2 += __ldcg(&g_part[kr][b_idx][u_idx + 2048]);
                z3 += __ldcg(&g_part[kr][b_idx][u_idx + 3072]);
            }
            float gi = tanhf(z0);
            float gf = tanhf(z1);
            float gg = tanhf(z2);
            float go = tanhf(z3);
            float cn = fmaf(gf, creg, gi * gg);
            float hn = go * tanhf(cn);
            if (tokv != 0) { creg = cn; hreg = hn; }
            g_hT[(t + 1) & 1][u_idx * 32 + b_idx] = hreg;

            // prefetch next step's gate inputs (off the critical path)
            if (t + 1 < 512) {
                const float* xr = g_xw + ((size_t)(t + 1) * 32 + b_idx) * 4096;
#pragma unroll
                for (int g = 0; g < 4; ++g) xwp[g] = __ldcs(xr + u_idx + g * 1024);
                tokv = g_tokens[b_idx * 512 + t + 1];
            }
        }
        grid_barrier();
    }

    out[b_idx * 1024 + u_idx]         = hreg;
    out[32768 + b_idx * 1024 + u_idx] = hreg;
    out[65536 + b_idx * 1024 + u_idx] = creg;
}

// ----------------------------------------------------------------------------
extern "C" void kernel_launch(void* const* d_in, const int* in_sizes, int n_in,
                              void* d_out, int out_size)
{
    const int*   tokens_raw = (const int*)  d_in[0];
    const float* emb        = (const float*)d_in[1];
    const float* W          = (const float*)d_in[2];
    const float* U          = (const float*)d_in[3];
    const float* bias       = (const float*)d_in[4];
    float*       out        = (float*)d_out;
    (void)in_sizes; (void)n_in; (void)out_size;

    embed_gemm_kernel<<<dim3(32, 128), 256>>>(tokens_raw, emb, W, bias);
    lstm_kernel<<<NCTA, 256>>>(tokens_raw, U, out);
}

// round 5
// speedup vs baseline: 1.6890x; 1.6036x over previous
#include <cuda_runtime.h>
#include <cuda_bf16.h>
#include <cstdint>
#include <cstddef>

// ----------------------------------------------------------------------------
// B=32, S=512, E=512, U=1024, G=4096.  out = (h, h, c) : 3*32*1024 f32
// LSTM recurrent GEMM on tensor cores via mma.sync bf16 (bf16x3 fp32 emulation)
// ----------------------------------------------------------------------------
#define NCTA 128

__device__ float          g_xw[(size_t)16384 * 4096];  // xW rows [t*32+b][4096]
__device__ float          g_part[4][32][4096];         // split-K partials
__device__ __nv_bfloat16  g_hh[2][32768];              // h hi, [b][u], double buf
__device__ __nv_bfloat16  g_hl[2][32768];              // h lo
__device__ uint4          g_pkA_hi[524288];            // Ut packed A-fragments hi
__device__ uint4          g_pkA_lo[524288];            // Ut packed A-fragments lo
__device__ int            g_tokens[16384];             // [b*512+t]
__device__ unsigned       g_cnt;
__device__ volatile unsigned g_gen;

// ---------------- helpers ----------------
__device__ __forceinline__ int detect_is64(const int* raw, int thr, int* s_flag)
{
    if (thr == 0) *s_flag = 1;
    __syncthreads();
    if (thr < 128 && raw[2 * thr + 1] != 0) *s_flag = 0;
    __syncthreads();
    return *s_flag;
}
__device__ __forceinline__ unsigned short bf_hi(float f, float& rem) {
    __nv_bfloat16 b = __float2bfloat16(f);
    rem = f - __bfloat162float(b);
    unsigned short u; memcpy(&u, &b, 2); return u;
}
__device__ __forceinline__ unsigned short bf_of(float f) {
    __nv_bfloat16 b = __float2bfloat16(f);
    unsigned short u; memcpy(&u, &b, 2); return u;
}
__device__ __forceinline__ uint32_t smem_u32(const void* p) {
    uint32_t a;
    asm("{ .reg .u64 t; cvta.to.shared.u64 t, %1; cvt.u32.u64 %0, t; }" : "=r"(a) : "l"(p));
    return a;
}
#define LDSM4(r0, r1, r2, r3, addr) \
    asm volatile("ldmatrix.sync.aligned.m8n8.x4.shared.b16 {%0,%1,%2,%3}, [%4];" \
                 : "=r"(r0), "=r"(r1), "=r"(r2), "=r"(r3) : "r"(addr))
#define MMA_BF16(d, ax, ay, az, aw, b0, b1) \
    asm volatile("mma.sync.aligned.m16n8k16.row.col.f32.bf16.bf16.f32 " \
                 "{%0,%1,%2,%3}, {%4,%5,%6,%7}, {%8,%9}, {%0,%1,%2,%3};" \
                 : "+f"((d)[0]), "+f"((d)[1]), "+f"((d)[2]), "+f"((d)[3]) \
                 : "r"(ax), "r"(ay), "r"(az), "r"(aw), "r"(b0), "r"(b1))

// ----------------------------------------------------------------------------
// pack Ut into per-thread mma A-fragment order.
// Slot idx = (((cta*8 + w)*16 + c)*32 + t):  a0..a3 for warp w, k-chunk c.
// A[m][k] = U[k][j(m)],  j(m) = (m>>5)*1024 + u0 + (m&31),  cta=(jb<<2)|ks.
// ----------------------------------------------------------------------------
__global__ void __launch_bounds__(256) pack_U_kernel(const float* __restrict__ U)
{
    int idx = blockIdx.x * 256 + threadIdx.x;       // 0..524287
    int t   = idx & 31;
    int c   = (idx >> 5) & 15;
    int w   = (idx >> 9) & 7;
    int cta = idx >> 12;
    int jb = cta >> 2, ks = cta & 3, u0 = jb << 5;
    int m0 = (w << 4) + (t >> 2), m1 = m0 + 8;
    int j0 = ((m0 >> 5) << 10) + u0 + (m0 & 31);
    int j1 = ((m1 >> 5) << 10) + u0 + (m1 & 31);
    int k0 = (ks << 8) + (c << 4) + ((t & 3) << 1);
    const float* U0 = U + (size_t)k0 * 4096;
    float f[4][2];
    f[0][0] = U0[j0];              f[0][1] = U0[4096 + j0];
    f[1][0] = U0[j1];              f[1][1] = U0[4096 + j1];
    f[2][0] = U0[8 * 4096 + j0];   f[2][1] = U0[9 * 4096 + j0];
    f[3][0] = U0[8 * 4096 + j1];   f[3][1] = U0[9 * 4096 + j1];
    uint32_t hi[4], lo[4];
#pragma unroll
    for (int r = 0; r < 4; ++r) {
        float rm0, rm1;
        unsigned short h0 = bf_hi(f[r][0], rm0), h1 = bf_hi(f[r][1], rm1);
        hi[r] = (uint32_t)h0 | ((uint32_t)h1 << 16);
        lo[r] = (uint32_t)bf_of(rm0) | ((uint32_t)bf_of(rm1) << 16);
    }
    g_pkA_hi[idx] = make_uint4(hi[0], hi[1], hi[2], hi[3]);
    g_pkA_lo[idx] = make_uint4(lo[0], lo[1], lo[2], lo[3]);
}

// ----------------------------------------------------------------------------
// Embed GEMM (round-1 FFMA version, proven): g_xw[r][n] = emb[tok(r)]@W + b
// ----------------------------------------------------------------------------
__global__ void __launch_bounds__(256) embed_gemm_kernel(
    const int*   __restrict__ raw,
    const float* __restrict__ emb,
    const float* __restrict__ W,
    const float* __restrict__ bias)
{
    __shared__ float As[2][16][132];
    __shared__ float Bs[2][16][128];
    __shared__ int s_is64;

    const int thr = threadIdx.x;
    const int is64 = detect_is64(raw, thr, &s_is64);
    const int n0 = blockIdx.x * 128;
    const int m0 = blockIdx.y * 128;
    const int tx = thr & 15;
    const int ty = thr >> 4;

    const float* aptr[2];
    int akq[2], am[2];
#pragma unroll
    for (int p = 0; p < 2; ++p) {
        int idx = p * 256 + thr;
        am[p]  = idx >> 2;
        akq[p] = idx & 3;
        int r  = m0 + am[p];
        int ti = (r & 31) * 512 + (r >> 5);
        int tok = is64 ? raw[2 * ti] : raw[ti];
        aptr[p] = emb + (size_t)tok * 512;
    }
    int bkk[2], bc4[2];
#pragma unroll
    for (int p = 0; p < 2; ++p) {
        int idx = p * 256 + thr;
        bkk[p] = idx >> 5;
        bc4[p] = idx & 31;
    }
#pragma unroll
    for (int p = 0; p < 2; ++p) {
        float4 v = *(const float4*)(aptr[p] + akq[p] * 4);
        As[0][akq[p] * 4 + 0][am[p]] = v.x;
        As[0][akq[p] * 4 + 1][am[p]] = v.y;
        As[0][akq[p] * 4 + 2][am[p]] = v.z;
        As[0][akq[p] * 4 + 3][am[p]] = v.w;
        float4 w4 = *(const float4*)(W + (size_t)bkk[p] * 4096 + n0 + bc4[p] * 4);
        *(float4*)&Bs[0][bkk[p]][bc4[p] * 4] = w4;
    }
    __syncthreads();

    float acc[8][8];
#pragma unroll
    for (int i = 0; i < 8; ++i)
#pragma unroll
        for (int j = 0; j < 8; ++j) acc[i][j] = 0.f;

    int buf = 0;
    for (int k0 = 0; k0 < 512; k0 += 16) {
        float4 an[2], bn[2];
        const bool more = (k0 + 16) < 512;
        if (more) {
#pragma unroll
            for (int p = 0; p < 2; ++p) {
                an[p] = *(const float4*)(aptr[p] + k0 + 16 + akq[p] * 4);
                bn[p] = *(const float4*)(W + (size_t)(k0 + 16 + bkk[p]) * 4096 + n0 + bc4[p] * 4);
            }
        }
#pragma unroll
        for (int kk = 0; kk < 16; ++kk) {
            float4 a0 = *(const float4*)&As[buf][kk][ty * 4];
            float4 a1 = *(const float4*)&As[buf][kk][64 + ty * 4];
            float4 b0 = *(const float4*)&Bs[buf][kk][tx * 4];
            float4 b1 = *(const float4*)&Bs[buf][kk][64 + tx * 4];
            float av[8] = {a0.x, a0.y, a0.z, a0.w, a1.x, a1.y, a1.z, a1.w};
            float bv[8] = {b0.x, b0.y, b0.z, b0.w, b1.x, b1.y, b1.z, b1.w};
#pragma unroll
            for (int i = 0; i < 8; ++i)
#pragma unroll
                for (int j = 0; j < 8; ++j)
                    acc[i][j] = fmaf(av[i], bv[j], acc[i][j]);
        }
        if (more) {
            int nb = buf ^ 1;
#pragma unroll
            for (int p = 0; p < 2; ++p) {
                As[nb][akq[p] * 4 + 0][am[p]] = an[p].x;
                As[nb][akq[p] * 4 + 1][am[p]] = an[p].y;
                As[nb][akq[p] * 4 + 2][am[p]] = an[p].z;
                As[nb][akq[p] * 4 + 3][am[p]] = an[p].w;
                *(float4*)&Bs[nb][bkk[p]][bc4[p] * 4] = bn[p];
            }
        }
        __syncthreads();
        buf ^= 1;
    }

    float4 bb0 = *(const float4*)(bias + n0 + tx * 4);
    float4 bb1 = *(const float4*)(bias + n0 + 64 + tx * 4);
#pragma unroll
    for (int i = 0; i < 8; ++i) {
        int m = (i < 4) ? (ty * 4 + i) : (64 + ty * 4 + i - 4);
        float* o = g_xw + (size_t)(m0 + m) * 4096 + n0;
        *(float4*)(o + tx * 4) = make_float4(acc[i][0] + bb0.x, acc[i][1] + bb0.y,
                                             acc[i][2] + bb0.z, acc[i][3] + bb0.w);
        *(float4*)(o + 64 + tx * 4) = make_float4(acc[i][4] + bb1.x, acc[i][5] + bb1.y,
                                                  acc[i][6] + bb1.z, acc[i][7] + bb1.w);
    }
}

// ---------------- grid barrier ----------------
__device__ __forceinline__ void grid_barrier()
{
    __threadfence();
    __syncthreads();
    if (threadIdx.x == 0) {
        unsigned g = g_gen;
        if (atomicAdd(&g_cnt, 1u) == (NCTA - 1u)) {
            g_cnt = 0;
            __threadfence();
            g_gen = g + 1;
        } else {
            while (g_gen == g) { __nanosleep(32); }
        }
    }
    __syncthreads();
}

// ----------------------------------------------------------------------------
// LSTM scan: 128 CTAs, 256 thr (8 warps).  cta = jb*4 + ks.
// Phase 1 (mma.sync bf16x3): part[ks][b][M] over k in [ks*256,+256), warp w
//   owns rows m in [w*16,w*16+16) of the 128-row tile (M = gate*1024+u0+(m&31)).
//   A from prepacked global (LDG.128), B (h slice) staged to smem + ldmatrix.
// Phase 2: thread (b,u) reduces 4 partials, gates, mask, writes h hi/lo.
// ----------------------------------------------------------------------------
__global__ void __launch_bounds__(256, 1) lstm_kernel(
    const int* __restrict__ raw, float* __restrict__ out)
{
    __shared__ __align__(16) char Bsm[2 * 16896];   // [half][32 rows][528B]
    __shared__ int s_is64;

    const int thr  = threadIdx.x;
    const int lane = thr & 31;
    const int w    = thr >> 5;
    const int cta  = blockIdx.x;
    const int ks   = cta & 3;
    const int u0   = (cta >> 2) << 5;
    const int is64 = detect_is64(raw, thr, &s_is64);

    // prologue: convert token slice, zero h buffer 0
    if (thr < 128) {
        int i = cta * 128 + thr;
        g_tokens[i] = is64 ? raw[2 * i] : raw[i];
    }
    const int tid = cta * 256 + thr;         // (b,u) ownership: b=tid>>10, u=tid&1023
    const int b_idx = tid >> 10, u_idx = tid & 1023;
    {
        unsigned short z = 0;
        *(unsigned short*)&g_hh[0][tid] = z;
        *(unsigned short*)&g_hl[0][tid] = z;
    }
    grid_barrier();

    float hreg = 0.f, creg = 0.f;
    float xwp[4];
    int tokv;
    {
        const float* xr = g_xw + (size_t)b_idx * 4096 + u_idx;
#pragma unroll
        for (int g = 0; g < 4; ++g) xwp[g] = __ldcs(xr + g * 1024);
        tokv = g_tokens[b_idx * 512];
    }

    // mma geometry
    const uint32_t sbB = smem_u32(Bsm);
    const int tile = lane >> 3, rsel = lane & 7;
    const int nrowoff = ((tile >> 1) & 1) * 8 + rsel;   // +8 for tiles 2,3
    const int koff    = (tile & 1) * 16;                // +16B for tiles 1,3
    const int abase   = (cta * 8 + w) * 512 + lane;
    // partial-store row mapping
    const int m_r  = (w << 4) + (lane >> 2);
    const int Mg0  = ((m_r >> 5) << 10) + u0 + (m_r & 31);
    const int m_r8 = m_r + 8;
    const int Mg8  = ((m_r8 >> 5) << 10) + u0 + (m_r8 & 31);

    for (int t = 0; t < 512; ++t) {
        // ---- stage B: h slice [32][256] hi+lo into smem (pitch 528) ----
        const __nv_bfloat16* hsrc0 = g_hh[t & 1] + ks * 256;
        const __nv_bfloat16* hsrc1 = g_hl[t & 1] + ks * 256;
#pragma unroll
        for (int ii = 0; ii < 8; ++ii) {
            int idx  = ii * 256 + thr;            // 0..2047
            int hsel = idx >> 10;
            int rq   = idx & 1023;
            int row  = rq >> 5, q = rq & 31;
            const __nv_bfloat16* src = (hsel ? hsrc1 : hsrc0) + row * 1024;
            uint4 v = __ldcg((const uint4*)src + q);
            *(uint4*)(Bsm + hsel * 16896 + row * 528 + q * 16) = v;
        }
        __syncthreads();

        // ---- mma mainloop over 16 k-chunks ----
        float d[4][4];
#pragma unroll
        for (int nf = 0; nf < 4; ++nf)
#pragma unroll
            for (int i = 0; i < 4; ++i) d[nf][i] = 0.f;

#pragma unroll 4
        for (int c = 0; c < 16; ++c) {
            uint4 ah = __ldg(&g_pkA_hi[abase + c * 32]);
            uint4 al = __ldg(&g_pkA_lo[abase + c * 32]);
            uint32_t bh[8], bl[8];
            uint32_t a0 = sbB + (0 + nrowoff) * 528 + c * 32 + koff;
            uint32_t a1 = sbB + (16 + nrowoff) * 528 + c * 32 + koff;
            LDSM4(bh[0], bh[1], bh[2], bh[3], a0);
            LDSM4(bh[4], bh[5], bh[6], bh[7], a1);
            LDSM4(bl[0], bl[1], bl[2], bl[3], a0 + 16896);
            LDSM4(bl[4], bl[5], bl[6], bl[7], a1 + 16896);
#pragma unroll
            for (int nf = 0; nf < 4; ++nf) {
                MMA_BF16(d[nf], ah.x, ah.y, ah.z, ah.w, bh[nf * 2], bh[nf * 2 + 1]);
                MMA_BF16(d[nf], ah.x, ah.y, ah.z, ah.w, bl[nf * 2], bl[nf * 2 + 1]);
                MMA_BF16(d[nf], al.x, al.y, al.z, al.w, bh[nf * 2], bh[nf * 2 + 1]);
            }
        }

        // ---- store partials: part[ks][b][M] ----
#pragma unroll
        for (int nf = 0; nf < 4; ++nf) {
            int bcol = nf * 8 + ((lane & 3) << 1);
            g_part[ks][bcol][Mg0]     = d[nf][0];
            g_part[ks][bcol + 1][Mg0] = d[nf][1];
            g_part[ks][bcol][Mg8]     = d[nf][2];
            g_part[ks][bcol + 1][Mg8] = d[nf][3];
        }
        grid_barrier();

        // ---- phase 2: reduce + gates ----
        {
            float z0 = xwp[0], z1 = xwp[1], z2 = xwp[2], z3 = xwp[3];
#pragma unroll
            for (int kr = 0; kr < 4; ++kr) {
                z0 += __ldcg(&g_part[kr][b_idx][u_idx]);
                z1 += __ldcg(&g_part[kr][b_idx][u_idx + 1024]);
                z2 += __ldcg(&g_part[kr][b_idx][u_idx + 2048]);
                z3 += __ldcg(&g_part[kr][b_idx][u_idx + 3072]);
            }
            float gi = tanhf(z0);
            float gf = tanhf(z1);
            float gg = tanhf(z2);
            float go = tanhf(z3);
            float cn = fmaf(gf, creg, gi * gg);
            float hn = go * tanhf(cn);
            if (tokv != 0) { creg = cn; hreg = hn; }
            float rem;
            unsigned short hb = bf_hi(hreg, rem);
            *(unsigned short*)&g_hh[(t + 1) & 1][tid] = hb;
            *(unsigned short*)&g_hl[(t + 1) & 1][tid] = bf_of(rem);

            if (t + 1 < 512) {
                const float* xr = g_xw + ((size_t)(t + 1) * 32 + b_idx) * 4096 + u_idx;
#pragma unroll
                for (int g = 0; g < 4; ++g) xwp[g] = __ldcs(xr + g * 1024);
                tokv = g_tokens[b_idx * 512 + t + 1];
            }
        }
        grid_barrier();
    }

    out[b_idx * 1024 + u_idx]         = hreg;
    out[32768 + b_idx * 1024 + u_idx] = hreg;
    out[65536 + b_idx * 1024 + u_idx] = creg;
}

// ---------------- launch ----------------
extern "C" void kernel_launch(void* const* d_in, const int* in_sizes, int n_in,
                              void* d_out, int out_size)
{
    const int*   tokens_raw = (const int*)  d_in[0];
    const float* emb        = (const float*)d_in[1];
    const float* W          = (const float*)d_in[2];
    const float* U          = (const float*)d_in[3];
    const float* bias       = (const float*)d_in[4];
    float*       out        = (float*)d_out;
    (void)in_sizes; (void)n_in; (void)out_size;

    pack_U_kernel<<<2048, 256>>>(U);
    embed_gemm_kernel<<<dim3(32, 128), 256>>>(tokens_raw, emb, W, bias);
    lstm_kernel<<<NCTA, 256>>>(tokens_raw, out);
}